// round 1
// baseline (speedup 1.0000x reference)
#include <cuda_runtime.h>
#include <cuda_fp16.h>
#include <mma.h>
using namespace nvcuda;

// Problem constants (fixed shapes from reference: outputs [8192,64] f32, labels [8192] i32)
#define BQ 8192
#define DD 64
#define TILE 64
#define NB (BQ / TILE)                // 128 tile-rows
#define NTILES (NB * (NB + 1) / 2)    // 8256 upper-triangle tiles (incl. diagonal)

// Scratch (allocation-free rule: __device__ globals)
__device__ __half g_Ah[BQ * DD];      // fp16 copy of outputs
__device__ float  g_sq[BQ];           // row squared norms (of the fp16-rounded rows)
__device__ float  g_partial[NTILES];  // per-CTA partial sums (deterministic reduce)

// ---------------------------------------------------------------------------
// Kernel 1: convert f32 -> f16, compute row norms from the rounded values
// (so d2 is the exact squared distance of the fp16 vectors -> no cancellation
//  mismatch between the norm terms and the Gram term)
// ---------------------------------------------------------------------------
__global__ void prep_kernel(const float* __restrict__ outputs) {
    int row = blockIdx.x * blockDim.x + threadIdx.x;
    if (row >= BQ) return;
    const float* src = outputs + row * DD;
    __half* dst = g_Ah + (size_t)row * DD;
    float s = 0.f;
#pragma unroll
    for (int c = 0; c < DD; c += 4) {
        float4 v = *(const float4*)(src + c);
        __half h0 = __float2half_rn(v.x);
        __half h1 = __float2half_rn(v.y);
        __half h2 = __float2half_rn(v.z);
        __half h3 = __float2half_rn(v.w);
        float f0 = __half2float(h0), f1 = __half2float(h1);
        float f2 = __half2float(h2), f3 = __half2float(h3);
        s = fmaf(f0, f0, s); s = fmaf(f1, f1, s);
        s = fmaf(f2, f2, s); s = fmaf(f3, f3, s);
        dst[c + 0] = h0; dst[c + 1] = h1; dst[c + 2] = h2; dst[c + 3] = h3;
    }
    g_sq[row] = s;
}

// ---------------------------------------------------------------------------
// Kernel 2: one CTA per upper-triangle 64x64 tile.
//   Gram tile via wmma (fp16 in, fp32 accum) -> smem -> fused epilogue:
//   d2 = sq_i + sq_j - 2g ; dist = sqrt(sqrt(d2)) via 2x MUFU sqrt.approx ;
//   weight -1 / +5 by label match ; block-reduce to g_partial[blockIdx.x].
// ---------------------------------------------------------------------------
__global__ __launch_bounds__(128) void pair_kernel(const int* __restrict__ labels) {
    __shared__ __half sA[TILE][72];   // 72-elem ld: 144B rows, 16B aligned, dodges conflicts
    __shared__ __half sB[TILE][72];
    __shared__ float  sC[TILE][TILE];
    __shared__ float  sqA[TILE], sqB[TILE];
    __shared__ int    labA[TILE], labB[TILE];
    __shared__ float  wsum[4];

    const int t   = blockIdx.x;
    const int tid = threadIdx.x;

    // Decode linear tile id -> (bi, bj) with bi <= bj (row-major upper triangle).
    // off(r) = r*NB - r*(r-1)/2
    int bi = (int)((double)NB + 0.5 - sqrt(((double)NB + 0.5) * ((double)NB + 0.5) - 2.0 * (double)t));
    if (bi < 0) bi = 0;
    if (bi > NB - 1) bi = NB - 1;
    while (bi > 0 && (bi * NB - bi * (bi - 1) / 2) > t) bi--;
    while (((bi + 1) * NB - (bi + 1) * bi / 2) <= t) bi++;
    const int bj = bi + (t - (bi * NB - bi * (bi - 1) / 2));

    const int rowA0 = bi * TILE;
    const int rowB0 = bj * TILE;

    // Load A/B tiles (64 rows x 64 halves, 8-half vectors)
    for (int v = tid; v < TILE * DD / 8; v += 128) {
        int r = v >> 3;
        int c = (v & 7) * 8;
        *(int4*)&sA[r][c] = *(const int4*)&g_Ah[(size_t)(rowA0 + r) * DD + c];
        *(int4*)&sB[r][c] = *(const int4*)&g_Ah[(size_t)(rowB0 + r) * DD + c];
    }
    if (tid < TILE) {
        sqA[tid]  = g_sq[rowA0 + tid];
        sqB[tid]  = g_sq[rowB0 + tid];
        labA[tid] = labels[rowA0 + tid];
        labB[tid] = labels[rowB0 + tid];
    }
    __syncthreads();

    // Gram tile: C[i][j] = sum_k A_i[k] * B_j[k]  (B fragment loaded col_major)
    const int w  = tid >> 5;
    const int wr = (w >> 1) * 32;
    const int wc = (w & 1) * 32;

    wmma::fragment<wmma::accumulator, 16, 16, 16, float> cf[2][2];
#pragma unroll
    for (int mm = 0; mm < 2; mm++)
#pragma unroll
        for (int nn = 0; nn < 2; nn++)
            wmma::fill_fragment(cf[mm][nn], 0.f);

#pragma unroll
    for (int k = 0; k < 4; k++) {
        wmma::fragment<wmma::matrix_a, 16, 16, 16, __half, wmma::row_major> af[2];
        wmma::fragment<wmma::matrix_b, 16, 16, 16, __half, wmma::col_major> bf[2];
#pragma unroll
        for (int mm = 0; mm < 2; mm++)
            wmma::load_matrix_sync(af[mm], &sA[wr + 16 * mm][k * 16], 72);
#pragma unroll
        for (int nn = 0; nn < 2; nn++)
            wmma::load_matrix_sync(bf[nn], &sB[wc + 16 * nn][k * 16], 72);
#pragma unroll
        for (int mm = 0; mm < 2; mm++)
#pragma unroll
            for (int nn = 0; nn < 2; nn++)
                wmma::mma_sync(cf[mm][nn], af[mm], bf[nn], cf[mm][nn]);
    }
#pragma unroll
    for (int mm = 0; mm < 2; mm++)
#pragma unroll
        for (int nn = 0; nn < 2; nn++)
            wmma::store_matrix_sync(&sC[wr + 16 * mm][wc + 16 * nn], cf[mm][nn], TILE, wmma::mem_row_major);
    __syncthreads();

    // Fused epilogue (MUFU-bound part)
    float acc = 0.f;
    const bool diag = (bi == bj);
    for (int e = tid; e < TILE * TILE; e += 128) {
        int r = e >> 6;
        int c = e & 63;
        if (!diag || c > r) {
            float g  = sC[r][c];
            float d2 = fmaf(-2.f, g, sqA[r] + sqB[c]);
            d2 = fmaxf(d2, 0.f);
            float s1, s2;
            asm("sqrt.approx.f32 %0, %1;" : "=f"(s1) : "f"(d2));
            asm("sqrt.approx.f32 %0, %1;" : "=f"(s2) : "f"(s1));
            float wgt = (labA[r] == labB[c]) ? 5.f : -1.f;
            acc = fmaf(s2, wgt, acc);
        }
    }

    // Block reduce -> deterministic per-CTA partial
#pragma unroll
    for (int off = 16; off; off >>= 1)
        acc += __shfl_xor_sync(0xFFFFFFFFu, acc, off);
    if ((tid & 31) == 0) wsum[tid >> 5] = acc;
    __syncthreads();
    if (tid == 0)
        g_partial[blockIdx.x] = wsum[0] + wsum[1] + wsum[2] + wsum[3];
}

// ---------------------------------------------------------------------------
// Kernel 3: deterministic final reduction of 8256 partials
// ---------------------------------------------------------------------------
__global__ void reduce_kernel(float* __restrict__ out) {
    __shared__ float sh[256];
    float s = 0.f;
    for (int i = threadIdx.x; i < NTILES; i += 256)
        s += g_partial[i];
    sh[threadIdx.x] = s;
    __syncthreads();
    for (int off = 128; off; off >>= 1) {
        if (threadIdx.x < off) sh[threadIdx.x] += sh[threadIdx.x + off];
        __syncthreads();
    }
    if (threadIdx.x == 0) out[0] = sh[0];
}

extern "C" void kernel_launch(void* const* d_in, const int* in_sizes, int n_in,
                              void* d_out, int out_size) {
    const float* outputs = (const float*)d_in[0];
    const int*   labels  = (const int*)d_in[1];
    float*       out     = (float*)d_out;

    prep_kernel<<<BQ / 128, 128>>>(outputs);
    pair_kernel<<<NTILES, 128>>>(labels);
    reduce_kernel<<<1, 256>>>(out);
}

// round 2
// speedup vs baseline: 1.8732x; 1.8732x over previous
#include <cuda_runtime.h>
#include <cuda_fp16.h>
#include <cstdint>

// Shapes fixed by reference: outputs [8192,64] f32, labels [8192] i32
#define BQ 8192
#define DD 64
#define TM 128                       // tile rows (A side)
#define TN 128                       // tile cols (B side)
#define NB (BQ / TM)                 // 64 tile-rows
#define NTILES (NB * (NB + 1) / 2)   // 2080 upper-triangle tiles (incl. diagonal)

// Scratch (__device__ globals: allocation-free rule)
__device__ __half g_Ah[BQ * DD];
__device__ float  g_sq[BQ];
__device__ float  g_partial[NTILES];

// ---------------------------------------------------------------------------
// Kernel 1: f32 -> f16 + row squared norms (of the rounded values).
// Warp per row: lane holds 2 consecutive elements.
// ---------------------------------------------------------------------------
__global__ __launch_bounds__(256) void prep_kernel(const float* __restrict__ outputs) {
    const int row  = blockIdx.x * 8 + (threadIdx.x >> 5);
    const int lane = threadIdx.x & 31;
    float2 v = ((const float2*)(outputs + (size_t)row * DD))[lane];
    __half2 h = __floats2half2_rn(v.x, v.y);
    float f0 = __half2float(__low2half(h));
    float f1 = __half2float(__high2half(h));
    float s = fmaf(f0, f0, f1 * f1);
#pragma unroll
    for (int off = 16; off; off >>= 1)
        s += __shfl_xor_sync(0xFFFFFFFFu, s, off);
    ((__half2*)(g_Ah + (size_t)row * DD))[lane] = h;
    if (lane == 0) g_sq[row] = s;
}

// ---------------------------------------------------------------------------
// ldmatrix / mma helpers (m16n8k16 f16 -> f32, row.col)
// ---------------------------------------------------------------------------
__device__ __forceinline__ uint32_t smem_u32(const void* p) {
    return (uint32_t)__cvta_generic_to_shared(p);
}
__device__ __forceinline__ void ldmatrix_x4(uint32_t& r0, uint32_t& r1, uint32_t& r2, uint32_t& r3,
                                            uint32_t addr) {
    asm volatile("ldmatrix.sync.aligned.m8n8.x4.shared.b16 {%0,%1,%2,%3}, [%4];"
                 : "=r"(r0), "=r"(r1), "=r"(r2), "=r"(r3) : "r"(addr));
}
__device__ __forceinline__ void ldmatrix_x2(uint32_t& r0, uint32_t& r1, uint32_t addr) {
    asm volatile("ldmatrix.sync.aligned.m8n8.x2.shared.b16 {%0,%1}, [%2];"
                 : "=r"(r0), "=r"(r1) : "r"(addr));
}
__device__ __forceinline__ void mma16816(float* c, const uint32_t* a, const uint32_t* b) {
    asm volatile(
        "mma.sync.aligned.m16n8k16.row.col.f32.f16.f16.f32 "
        "{%0,%1,%2,%3}, {%4,%5,%6,%7}, {%8,%9}, {%0,%1,%2,%3};"
        : "+f"(c[0]), "+f"(c[1]), "+f"(c[2]), "+f"(c[3])
        : "r"(a[0]), "r"(a[1]), "r"(a[2]), "r"(a[3]), "r"(b[0]), "r"(b[1]));
}
__device__ __forceinline__ float qroot(float d2) {  // (d2)^(1/4), d2 >= 0
    float s1, s2;
    asm("sqrt.approx.f32 %0, %1;" : "=f"(s1) : "f"(d2));
    asm("sqrt.approx.f32 %0, %1;" : "=f"(s2) : "f"(s1));
    return s2;
}

// ---------------------------------------------------------------------------
// Kernel 2: one CTA per upper-triangle 128x128 tile. 8 warps, warp-tile 32x64.
// Gram accumulators stay in registers; fused epilogue (2x MUFU sqrt per pair).
// ---------------------------------------------------------------------------
#define PAD 72  // halves per smem row (144B: conflict-free ldmatrix, 16B aligned)

__global__ __launch_bounds__(256, 2) void pair_kernel(const int* __restrict__ labels) {
    __shared__ __half sA[TM][PAD];
    __shared__ __half sB[TN][PAD];
    __shared__ float  sqA[TM], sqB[TN];
    __shared__ int    labA[TM], labB[TN];
    __shared__ float  wsum[8];

    const int t   = blockIdx.x;
    const int tid = threadIdx.x;

    // Decode linear tile id -> (bi, bj), bi <= bj, row-major upper triangle.
    int bi = (int)((double)NB + 0.5 -
                   sqrt(((double)NB + 0.5) * ((double)NB + 0.5) - 2.0 * (double)t));
    if (bi < 0) bi = 0;
    if (bi > NB - 1) bi = NB - 1;
    while (bi > 0 && (bi * NB - bi * (bi - 1) / 2) > t) bi--;
    while (((bi + 1) * NB - (bi + 1) * bi / 2) <= t) bi++;
    const int bj = bi + (t - (bi * NB - bi * (bi - 1) / 2));
    const bool diag = (bi == bj);

    const int rowA0 = bi * TM;
    const int rowB0 = bj * TN;

    // Fill tiles: 128 rows x 8 int4-chunks each = 1024 int4 per tile
    for (int v = tid; v < TM * 8; v += 256) {
        int r = v >> 3;
        int c = (v & 7) * 8;
        *(int4*)&sA[r][c] = *(const int4*)&g_Ah[(size_t)(rowA0 + r) * DD + c];
        *(int4*)&sB[r][c] = *(const int4*)&g_Ah[(size_t)(rowB0 + r) * DD + c];
    }
    if (tid < TM) {
        sqA[tid]  = g_sq[rowA0 + tid];
        sqB[tid]  = g_sq[rowB0 + tid];
        labA[tid] = labels[rowA0 + tid];
        labB[tid] = labels[rowB0 + tid];
    }
    __syncthreads();

    // Warp tiling: 4 warps along M (32 rows each), 2 along N (64 cols each)
    const int w    = tid >> 5;
    const int lane = tid & 31;
    const int wrow = (w & 3) * 32;
    const int wcol = (w >> 2) * 64;
    const int g    = lane >> 2;   // group id (row within 8x8 quads)
    const int t4   = lane & 3;    // thread-in-group (col pair)

    float acc[2][8][4];
#pragma unroll
    for (int mi = 0; mi < 2; mi++)
#pragma unroll
        for (int ni = 0; ni < 8; ni++)
#pragma unroll
            for (int e = 0; e < 4; e++) acc[mi][ni][e] = 0.f;

    const int lq = lane >> 3;   // quad index 0..3 (for x4 address gen)
    const int lr = lane & 7;    // row within quad

#pragma unroll
    for (int k = 0; k < 4; k++) {
        const int kb = k * 16;
        uint32_t af[2][4];
#pragma unroll
        for (int mi = 0; mi < 2; mi++) {
            // x4 matrices: (m0, k0), (m0+8, k0), (m0, k0+8), (m0+8, k0+8)
            int m0 = wrow + 16 * mi;
            int arow = m0 + lr + ((lq & 1) ? 8 : 0);
            int acol = kb + ((lq & 2) ? 8 : 0);
            ldmatrix_x4(af[mi][0], af[mi][1], af[mi][2], af[mi][3],
                        smem_u32(&sA[arow][acol]));
        }
#pragma unroll
        for (int ni = 0; ni < 8; ni++) {
            uint32_t bf[2];
            // x2 matrices: (n0, k0), (n0, k0+8); addresses from lanes 0..15
            int n0 = wcol + 8 * ni;
            int l16 = lane & 15;
            int brow = n0 + (l16 & 7);
            int bcol = kb + ((l16 & 8) ? 8 : 0);
            ldmatrix_x2(bf[0], bf[1], smem_u32(&sB[brow][bcol]));
#pragma unroll
            for (int mi = 0; mi < 2; mi++)
                mma16816(acc[mi][ni], af[mi], bf);
        }
    }

    // Fused epilogue on register accumulators.
    // Element map: acc[mi][ni][2*h + p] -> row = wrow+16*mi+8*h+g, col = wcol+8*ni+2*t4+p
    float sqr[2][2];
    int   lr2[2][2];
    int   rloc[2][2];
#pragma unroll
    for (int mi = 0; mi < 2; mi++)
#pragma unroll
        for (int h = 0; h < 2; h++) {
            int r = wrow + 16 * mi + 8 * h + g;
            rloc[mi][h] = r;
            sqr[mi][h]  = sqA[r];
            lr2[mi][h]  = labA[r];
        }

    float accsum = 0.f;
#pragma unroll
    for (int ni = 0; ni < 8; ni++) {
        int c0 = wcol + 8 * ni + 2 * t4;
        float sc0 = sqB[c0],     sc1 = sqB[c0 + 1];
        int   lc0 = labB[c0],    lc1 = labB[c0 + 1];
#pragma unroll
        for (int mi = 0; mi < 2; mi++)
#pragma unroll
            for (int h = 0; h < 2; h++) {
                float sr = sqr[mi][h];
                int   lr_ = lr2[mi][h];
                // element p = 0
                {
                    float d2 = fmaf(-2.f, acc[mi][ni][2 * h + 0], sr + sc0);
                    float dist = qroot(fmaxf(d2, 0.f));
                    float wgt = (lr_ == lc0) ? 5.f : -1.f;
                    if (diag && c0 <= rloc[mi][h]) wgt = 0.f;
                    accsum = fmaf(dist, wgt, accsum);
                }
                // element p = 1
                {
                    float d2 = fmaf(-2.f, acc[mi][ni][2 * h + 1], sr + sc1);
                    float dist = qroot(fmaxf(d2, 0.f));
                    float wgt = (lr_ == lc1) ? 5.f : -1.f;
                    if (diag && (c0 + 1) <= rloc[mi][h]) wgt = 0.f;
                    accsum = fmaf(dist, wgt, accsum);
                }
            }
    }

    // Deterministic block reduce -> per-CTA partial
#pragma unroll
    for (int off = 16; off; off >>= 1)
        accsum += __shfl_xor_sync(0xFFFFFFFFu, accsum, off);
    if (lane == 0) wsum[w] = accsum;
    __syncthreads();
    if (tid == 0) {
        float s = 0.f;
#pragma unroll
        for (int i = 0; i < 8; i++) s += wsum[i];
        g_partial[blockIdx.x] = s;
    }
}

// ---------------------------------------------------------------------------
// Kernel 3: deterministic final reduction of 2080 partials
// ---------------------------------------------------------------------------
__global__ void reduce_kernel(float* __restrict__ out) {
    __shared__ float sh[256];
    float s = 0.f;
    for (int i = threadIdx.x; i < NTILES; i += 256)
        s += g_partial[i];
    sh[threadIdx.x] = s;
    __syncthreads();
    for (int off = 128; off; off >>= 1) {
        if (threadIdx.x < off) sh[threadIdx.x] += sh[threadIdx.x + off];
        __syncthreads();
    }
    if (threadIdx.x == 0) out[0] = sh[0];
}

extern "C" void kernel_launch(void* const* d_in, const int* in_sizes, int n_in,
                              void* d_out, int out_size) {
    const float* outputs = (const float*)d_in[0];
    const int*   labels  = (const int*)d_in[1];
    float*       out     = (float*)d_out;

    prep_kernel<<<BQ / 8, 256>>>(outputs);
    pair_kernel<<<NTILES, 256>>>(labels);
    reduce_kernel<<<1, 256>>>(out);
}